// round 7
// baseline (speedup 1.0000x reference)
#include <cuda_runtime.h>
#include <cstdint>

#define THREADS 512   // 128 query-pairs x 4 candidate-chunks
#define NCHUNK  4
#define QPT     2     // queries per thread

// Packed-fp32x2 helpers (sm_103a). Per-lane .rn rounding is bit-identical to
// scalar ops, preserving argmin bit-exactness vs the JAX reference.
#define MUL2(d, a, b) \
    asm("mul.rn.f32x2 %0, %1, %2;" : "=l"(d) : "l"(a), "l"(b))
#define ADD2(d, a, b) \
    asm("add.rn.f32x2 %0, %1, %2;" : "=l"(d) : "l"(a), "l"(b))
#define FMA2(d, a, b, c) \
    asm("fma.rn.f32x2 %0, %1, %2, %3;" : "=l"(d) : "l"(a), "l"(b), "l"(c))

__device__ __forceinline__ unsigned long long pack2(float lo, float hi) {
    unsigned long long r;
    asm("mov.b64 %0, {%1, %2};" : "=l"(r) : "f"(lo), "f"(hi));
    return r;
}
__device__ __forceinline__ void unpack2(float& lo, float& hi,
                                        unsigned long long v) {
    asm("mov.b64 {%0, %1}, %2;" : "=f"(lo), "=f"(hi) : "l"(v));
}

// Monotone map: float bits -> uint32 with unsigned order == float order.
__device__ __forceinline__ unsigned int fenc(float f) {
    unsigned int b = __float_as_uint(f);
    return b ^ (((unsigned int)((int)b >> 31)) | 0x80000000u);
}
__device__ __forceinline__ float fdec(unsigned int e) {
    unsigned int b = (e & 0x80000000u) ? (e ^ 0x80000000u) : ~e;
    return __uint_as_float(b);
}

// Global scratch: packed (enc(dist) << 32 | idx) per query, atomicMin-merged
// across the two candidate-half CTAs. 2*(N+M) entries for B=2, N=M=8192.
__device__ unsigned long long g_scratch[32768];

__global__ void init_kernel(int total) {
    int t = blockIdx.x * blockDim.x + threadIdx.x;
    if (t < total) g_scratch[t] = ~0ULL;
}

__global__ void decode_kernel(float* __restrict__ out, int total) {
    int t = blockIdx.x * blockDim.x + threadIdx.x;
    if (t < total) {
        unsigned long long key = g_scratch[t];
        out[t]         = fdec((unsigned int)(key >> 32));
        out[total + t] = (float)(unsigned int)(key & 0xFFFFFFFFu);
    }
}

// Chamfer distance. blockIdx.z = dir*2 + half: each CTA scans HALF the
// candidate set (4096 pts, 64KB smem) for all 256 of its query lanes, so two
// CTAs fit per SM (8 warps/SMSP). Per-query partials merge via atomicMin on
// the packed key (dist-then-index order = first-occurrence argmin).
// Candidates cached pair-SoA, viewed as ulonglong2 so each LDS.128 quad IS
// two packed f32x2 operands. All arithmetic uses the exact JAX reference
// rounding sequence (see earlier rounds) for bit-exact argmin.
__global__ __launch_bounds__(THREADS, 2)
void chamfer_kernel(const float* __restrict__ xyz1,
                    const float* __restrict__ xyz2,
                    int N, int M, int B) {
    extern __shared__ float4 sh[];
    __shared__ unsigned long long red[QPT][THREADS];

    const int dir  = blockIdx.z >> 1;
    const int half = blockIdx.z & 1;
    const int b    = blockIdx.y;

    const float* q;
    const float* c;
    int Nq, Nc, obase;
    if (dir == 0) {
        q = xyz1; c = xyz2; Nq = N; Nc = M;
        obase = b * N;                 // dist1 region
    } else {
        q = xyz2; c = xyz1; Nq = M; Nc = N;
        obase = B * N + b * M;         // dist2 region
    }

    const int Nh    = Nc >> 1;         // candidates in this half (4096)
    const int hbase = half * Nh;       // global candidate offset

    // ---- fill shared memory (pair layout), reference rounding for |c|^2 ----
    const float* cb = c + (size_t)b * Nc * 3 + (size_t)hbase * 3;
    const int npairs = Nh >> 1;
    for (int p = threadIdx.x; p < npairs; p += THREADS) {
        float x0 = cb[6 * p + 0], y0 = cb[6 * p + 1], z0 = cb[6 * p + 2];
        float x1 = cb[6 * p + 3], y1 = cb[6 * p + 4], z1 = cb[6 * p + 5];
        float w0 = __fadd_rn(__fadd_rn(__fmul_rn(x0, x0), __fmul_rn(y0, y0)),
                             __fmul_rn(z0, z0));
        float w1 = __fadd_rn(__fadd_rn(__fmul_rn(x1, x1), __fmul_rn(y1, y1)),
                             __fmul_rn(z1, z1));
        sh[2 * p]     = make_float4(x0, x1, y0, y1);
        sh[2 * p + 1] = make_float4(z0, z1, w0, w1);
    }
    __syncthreads();

    const ulonglong2* sh2 = reinterpret_cast<const ulonglong2*>(sh);

    const int qp    = threadIdx.x & 127;   // query pair (0..127)
    const int chunk = threadIdx.x >> 7;    // candidate chunk (0..3)

    float ax[QPT], ay[QPT], az[QPT], sq[QPT];
    unsigned long long AX[QPT], AY[QPT], AZ[QPT], SQ[QPT];
#pragma unroll
    for (int k = 0; k < QPT; k++) {
        const int lane = QPT * qp + k;
        const int i = lane * gridDim.x + blockIdx.x;   // interleaved, balanced
        const int iq = (i < Nq) ? i : 0;
        const float* qpt = q + ((size_t)b * Nq + iq) * 3;
        ax[k] = qpt[0]; ay[k] = qpt[1]; az[k] = qpt[2];
        sq[k] = __fadd_rn(__fadd_rn(__fmul_rn(ax[k], ax[k]),
                                    __fmul_rn(ay[k], ay[k])),
                          __fmul_rn(az[k], az[k]));
        AX[k] = pack2(ax[k], ax[k]); AY[k] = pack2(ay[k], ay[k]);
        AZ[k] = pack2(az[k], az[k]); SQ[k] = pack2(sq[k], sq[k]);
    }
    const unsigned long long M22 = pack2(-2.0f, -2.0f);

    const int csz   = Nh / NCHUNK;         // 1024
    const int cbase = chunk * csz;         // local candidate base

    float best[QPT];
    int   bj[QPT];
#pragma unroll
    for (int k = 0; k < QPT; k++) { best[k] = 3.402823466e38f; bj[k] = cbase; }

    for (int j = cbase; j < cbase + csz; j += 8) {
        float e[QPT][8];
#pragma unroll
        for (int p = 0; p < 4; p++) {
            ulonglong2 A2 = sh2[j + 2 * p];      // (x0,x1),(y0,y1)
            ulonglong2 B2 = sh2[j + 2 * p + 1];  // (z0,z1),(w0,w1)
#pragma unroll
            for (int k = 0; k < QPT; k++) {
                unsigned long long t0, t1, t2, s2, r2;
                MUL2(t0, A2.x, AX[k]);
                FMA2(t1, A2.y, AY[k], t0);
                FMA2(t2, B2.x, AZ[k], t1);
                ADD2(s2, SQ[k], B2.y);
                FMA2(r2, M22, t2, s2);
                unpack2(e[k][2 * p], e[k][2 * p + 1], r2);
            }
        }
#pragma unroll
        for (int k = 0; k < QPT; k++) {
            float m01 = fminf(e[k][0], e[k][1]);
            float m23 = fminf(e[k][2], e[k][3]);
            float m45 = fminf(e[k][4], e[k][5]);
            float m67 = fminf(e[k][6], e[k][7]);
            float m03 = fminf(m01, m23);
            float m47 = fminf(m45, m67);
            float bm  = fminf(m03, m47);
            if (bm < best[k]) bj[k] = j;   // strict < : earliest block wins
            best[k] = fminf(best[k], bm);
        }
    }

    // ---- recover index within each winning block (first occurrence) ----
#pragma unroll
    for (int k = 0; k < QPT; k++) {
        int kwin = 0;
#pragma unroll
        for (int kk = 7; kk >= 0; kk--) {
            int p = kk >> 1, lane = kk & 1;
            float4 A  = sh[bj[k] + 2 * p];
            float4 Bv = sh[bj[k] + 2 * p + 1];
            float cx = lane ? A.y  : A.x;
            float cy = lane ? A.w  : A.z;
            float cz = lane ? Bv.y : Bv.x;
            float cw = lane ? Bv.w : Bv.z;
            float cr = fmaf(cz, az[k], fmaf(cy, ay[k], __fmul_rn(cx, ax[k])));
            float ek = fmaf(-2.0f, cr, __fadd_rn(sq[k], cw));
            if (ek == best[k]) kwin = kk;  // descending: smallest k survives
        }
        unsigned int gidx = (unsigned int)(hbase + bj[k] + kwin);
        red[k][threadIdx.x] =
            ((unsigned long long)fenc(best[k]) << 32) | gidx;
    }
    __syncthreads();

    // ---- merge the 4 chunks, then one atomicMin per query lane ----------
    if (threadIdx.x < 256) {
        const int l  = threadIdx.x;        // query lane 0..255
        const int qi = l * gridDim.x + blockIdx.x;
        if (qi < Nq) {
            const int ql = l & 1;          // query slot within pair
            const int pp = l >> 1;         // pair id
            unsigned long long r = red[ql][pp];
#pragma unroll
            for (int cth = 1; cth < NCHUNK; cth++) {
                unsigned long long rc = red[ql][cth * 128 + pp];
                if (rc < r) r = rc;        // key order = (dist, idx) asc
            }
            atomicMin(&g_scratch[obase + qi], r);
        }
    }
}

extern "C" void kernel_launch(void* const* d_in, const int* in_sizes, int n_in,
                              void* d_out, int out_size) {
    const float* xyz1 = (const float*)d_in[0];
    const float* xyz2 = (const float*)d_in[1];
    float* out = (float*)d_out;

    const int B = 2;
    const int N = in_sizes[0] / (3 * B);
    const int M = in_sizes[1] / (3 * B);
    const int maxNM = (N > M) ? N : M;
    const int total = B * (N + M);         // 32768 scratch/dist entries

    const size_t shmem = (size_t)(maxNM / 2) * sizeof(float4);  // 64 KB
    cudaFuncSetAttribute(chamfer_kernel,
                         cudaFuncAttributeMaxDynamicSharedMemorySize,
                         (int)shmem);

    init_kernel<<<(total + 255) / 256, 256>>>(total);

    // 37 x 2 x 4 = 296 CTAs: two per SM (dir x half in z), queries interleaved.
    dim3 grid(37, B, 4);
    chamfer_kernel<<<grid, THREADS, shmem>>>(xyz1, xyz2, N, M, B);

    decode_kernel<<<(total + 255) / 256, 256>>>(out, total);
}

// round 8
// speedup vs baseline: 1.0899x; 1.0899x over previous
#include <cuda_runtime.h>
#include <cstdint>

#define THREADS 512   // 128 query-pairs x 4 candidate-chunks
#define NCHUNK  4
#define QPT     2     // queries per thread

// Packed-fp32x2 helpers (sm_103a). Per-lane .rn rounding is bit-identical to
// scalar ops, preserving argmin bit-exactness vs the JAX reference.
#define MUL2(d, a, b) \
    asm("mul.rn.f32x2 %0, %1, %2;" : "=l"(d) : "l"(a), "l"(b))
#define ADD2(d, a, b) \
    asm("add.rn.f32x2 %0, %1, %2;" : "=l"(d) : "l"(a), "l"(b))
#define FMA2(d, a, b, c) \
    asm("fma.rn.f32x2 %0, %1, %2, %3;" : "=l"(d) : "l"(a), "l"(b), "l"(c))

__device__ __forceinline__ unsigned long long pack2(float lo, float hi) {
    unsigned long long r;
    asm("mov.b64 %0, {%1, %2};" : "=l"(r) : "f"(lo), "f"(hi));
    return r;
}
__device__ __forceinline__ void unpack2(float& lo, float& hi,
                                        unsigned long long v) {
    asm("mov.b64 {%0, %1}, %2;" : "=f"(lo), "=f"(hi) : "l"(v));
}

// Chamfer distance, both directions fused via blockIdx.z.
// Candidates cached in smem pair-SoA, viewed as ulonglong2 so each LDS.128
// register quad IS two packed f32x2 operands:
//   sh2[2p]   = ((x0,x1),(y0,y1))
//   sh2[2p+1] = ((z0,z1),(w0,w1))   w = |c|^2 with reference rounding
// Each thread owns TWO queries and scans one of 4 candidate chunks (2048).
// The scan is explicitly software-pipelined: the next 8-candidate block's
// smem data is prefetched into a second register buffer before computing on
// the current one, hiding the ~29cyc LDS latency behind a full block of math.
__global__ __launch_bounds__(THREADS, 1)
void chamfer_kernel(const float* __restrict__ xyz1,
                    const float* __restrict__ xyz2,
                    float* __restrict__ out,
                    int N, int M, int B) {
    extern __shared__ float4 sh[];
    __shared__ float2 red[QPT][THREADS];   // per-query-slot (best, idx)

    const int dir = blockIdx.z;
    const int b   = blockIdx.y;

    const float* q;
    const float* c;
    int Nq, Nc;
    float* dist_out;
    float* idx_out;
    if (dir == 0) {
        q = xyz1; c = xyz2; Nq = N; Nc = M;
        dist_out = out;                                        // dist1
        idx_out  = out + (size_t)B * (N + M);                  // idx1
    } else {
        q = xyz2; c = xyz1; Nq = M; Nc = N;
        dist_out = out + (size_t)B * N;                        // dist2
        idx_out  = out + (size_t)B * (N + M) + (size_t)B * N;  // idx2
    }

    // ---- fill shared memory (pair layout), reference rounding for |c|^2 ----
    const float* cb = c + (size_t)b * Nc * 3;
    const int npairs = Nc >> 1;
    for (int p = threadIdx.x; p < npairs; p += THREADS) {
        float x0 = cb[6 * p + 0], y0 = cb[6 * p + 1], z0 = cb[6 * p + 2];
        float x1 = cb[6 * p + 3], y1 = cb[6 * p + 4], z1 = cb[6 * p + 5];
        float w0 = __fadd_rn(__fadd_rn(__fmul_rn(x0, x0), __fmul_rn(y0, y0)),
                             __fmul_rn(z0, z0));
        float w1 = __fadd_rn(__fadd_rn(__fmul_rn(x1, x1), __fmul_rn(y1, y1)),
                             __fmul_rn(z1, z1));
        sh[2 * p]     = make_float4(x0, x1, y0, y1);
        sh[2 * p + 1] = make_float4(z0, z1, w0, w1);
    }
    __syncthreads();

    const ulonglong2* sh2 = reinterpret_cast<const ulonglong2*>(sh);

    const int qp    = threadIdx.x & 127;   // query pair (0..127)
    const int chunk = threadIdx.x >> 7;    // candidate chunk (0..3)

    float ax[QPT], ay[QPT], az[QPT], sq[QPT];
    unsigned long long AX[QPT], AY[QPT], AZ[QPT], SQ[QPT];
#pragma unroll
    for (int k = 0; k < QPT; k++) {
        const int lane = QPT * qp + k;
        const int i = lane * gridDim.x + blockIdx.x;   // interleaved, balanced
        const int iq = (i < Nq) ? i : 0;
        const float* qpt = q + ((size_t)b * Nq + iq) * 3;
        ax[k] = qpt[0]; ay[k] = qpt[1]; az[k] = qpt[2];
        sq[k] = __fadd_rn(__fadd_rn(__fmul_rn(ax[k], ax[k]),
                                    __fmul_rn(ay[k], ay[k])),
                          __fmul_rn(az[k], az[k]));
        AX[k] = pack2(ax[k], ax[k]); AY[k] = pack2(ay[k], ay[k]);
        AZ[k] = pack2(az[k], az[k]); SQ[k] = pack2(sq[k], sq[k]);
    }
    const unsigned long long M22 = pack2(-2.0f, -2.0f);

    const int csz   = Nc / NCHUNK;         // 2048
    const int cbase = chunk * csz;
    const int cend  = cbase + csz;

    float best0 = 3.402823466e38f, best1 = 3.402823466e38f;
    int   bj0 = cbase, bj1 = cbase;

    // One 8-candidate compute step on a register buffer bf[8].
#define STEP(bf, jb)                                                        \
    {                                                                       \
        float e0[8], e1[8];                                                 \
        _Pragma("unroll")                                                   \
        for (int p = 0; p < 4; p++) {                                       \
            ulonglong2 A2 = bf[2 * p];                                      \
            ulonglong2 B2 = bf[2 * p + 1];                                  \
            unsigned long long t0, t1, t2, s2, r2;                          \
            MUL2(t0, A2.x, AX[0]);                                          \
            FMA2(t1, A2.y, AY[0], t0);                                      \
            FMA2(t2, B2.x, AZ[0], t1);                                      \
            ADD2(s2, SQ[0], B2.y);                                          \
            FMA2(r2, M22, t2, s2);                                          \
            unpack2(e0[2 * p], e0[2 * p + 1], r2);                          \
            MUL2(t0, A2.x, AX[1]);                                          \
            FMA2(t1, A2.y, AY[1], t0);                                      \
            FMA2(t2, B2.x, AZ[1], t1);                                      \
            ADD2(s2, SQ[1], B2.y);                                          \
            FMA2(r2, M22, t2, s2);                                          \
            unpack2(e1[2 * p], e1[2 * p + 1], r2);                          \
        }                                                                   \
        float a01 = fminf(e0[0], e0[1]), a23 = fminf(e0[2], e0[3]);         \
        float a45 = fminf(e0[4], e0[5]), a67 = fminf(e0[6], e0[7]);         \
        float a03 = fminf(a01, a23),     a47 = fminf(a45, a67);             \
        float bm0 = fminf(a03, a47);                                        \
        float b01 = fminf(e1[0], e1[1]), b23 = fminf(e1[2], e1[3]);         \
        float b45 = fminf(e1[4], e1[5]), b67 = fminf(e1[6], e1[7]);         \
        float b03 = fminf(b01, b23),     b47 = fminf(b45, b67);             \
        float bm1 = fminf(b03, b47);                                        \
        if (bm0 < best0) bj0 = (jb);    /* strict <: earliest block wins */ \
        best0 = fminf(best0, bm0);                                          \
        if (bm1 < best1) bj1 = (jb);                                        \
        best1 = fminf(best1, bm1);                                          \
    }

    // Software-pipelined scan: prefetch block j+8 / j+16 while computing.
    ulonglong2 b0[8], b1[8];
#pragma unroll
    for (int t = 0; t < 8; t++) b0[t] = sh2[cbase + t];

    for (int j = cbase; j < cend; j += 16) {
        const int j1 = j + 8;                              // csz % 16 == 0
        const int j2 = (j + 16 < cend) ? (j + 16) : cbase; // safe wrap
#pragma unroll
        for (int t = 0; t < 8; t++) b1[t] = sh2[j1 + t];
        STEP(b0, j);
#pragma unroll
        for (int t = 0; t < 8; t++) b0[t] = sh2[j2 + t];
        STEP(b1, j1);
    }
#undef STEP

    // ---- recover index within each winning block (first occurrence) ----
    int kw0 = 0, kw1 = 0;
#pragma unroll
    for (int kk = 7; kk >= 0; kk--) {
        int p = kk >> 1, lane = kk & 1;
        {
            float4 A  = sh[bj0 + 2 * p];
            float4 Bv = sh[bj0 + 2 * p + 1];
            float cx = lane ? A.y  : A.x;
            float cy = lane ? A.w  : A.z;
            float cz = lane ? Bv.y : Bv.x;
            float cw = lane ? Bv.w : Bv.z;
            float cr = fmaf(cz, az[0], fmaf(cy, ay[0], __fmul_rn(cx, ax[0])));
            float ek = fmaf(-2.0f, cr, __fadd_rn(sq[0], cw));
            if (ek == best0) kw0 = kk;  // descending: smallest k survives
        }
        {
            float4 A  = sh[bj1 + 2 * p];
            float4 Bv = sh[bj1 + 2 * p + 1];
            float cx = lane ? A.y  : A.x;
            float cy = lane ? A.w  : A.z;
            float cz = lane ? Bv.y : Bv.x;
            float cw = lane ? Bv.w : Bv.z;
            float cr = fmaf(cz, az[1], fmaf(cy, ay[1], __fmul_rn(cx, ax[1])));
            float ek = fmaf(-2.0f, cr, __fadd_rn(sq[1], cw));
            if (ek == best1) kw1 = kk;
        }
    }

    red[0][threadIdx.x] = make_float2(best0, (float)(bj0 + kw0));
    red[1][threadIdx.x] = make_float2(best1, (float)(bj1 + kw1));
    __syncthreads();

    // ---- merge the 4 chunks; ascending chunk order, strict < keeps the
    //      earliest chunk (smaller candidate index) on exact ties ----------
    if (threadIdx.x < 256) {
        const int l  = threadIdx.x;        // query lane 0..255
        const int qi = l * gridDim.x + blockIdx.x;
        if (qi < Nq) {
            const int ql = l & 1;          // query slot within pair
            const int pp = l >> 1;         // pair id
            float2 r = red[ql][pp];        // chunk 0
#pragma unroll
            for (int cth = 1; cth < NCHUNK; cth++) {
                float2 rc = red[ql][cth * 128 + pp];
                if (rc.x < r.x) r = rc;
            }
            dist_out[(size_t)b * Nq + qi] = r.x;
            idx_out [(size_t)b * Nq + qi] = r.y;
        }
    }
}

extern "C" void kernel_launch(void* const* d_in, const int* in_sizes, int n_in,
                              void* d_out, int out_size) {
    const float* xyz1 = (const float*)d_in[0];
    const float* xyz2 = (const float*)d_in[1];
    float* out = (float*)d_out;

    const int B = 2;
    const int N = in_sizes[0] / (3 * B);
    const int M = in_sizes[1] / (3 * B);
    const int maxNM = (N > M) ? N : M;

    const size_t shmem = (size_t)maxNM * sizeof(float4);  // 128 KB for 8192
    cudaFuncSetAttribute(chamfer_kernel,
                         cudaFuncAttributeMaxDynamicSharedMemorySize,
                         (int)shmem);

    // 37 * 2 * 2 = 148 CTAs: one per SM, queries interleaved for balance.
    dim3 grid(37, B, 2);
    chamfer_kernel<<<grid, THREADS, shmem>>>(xyz1, xyz2, out, N, M, B);
}